// round 13
// baseline (speedup 1.0000x reference)
#include <cuda_runtime.h>
#include <cuda_bf16.h>

#define NMAX   100000
#define EMAX   1600000
#define HF     64          // HEADS * OUT_FEATS
#define HEADS  4
#define INF    128
#define BUCKET 128         // slots per node (max observed degree ~35; guarded)

typedef unsigned long long ull;

// ------------------------- device scratch (no allocs) -----------------------
// g_cnt relies on module-load zero-init for the first run; agg_kernel re-zeroes
// it after use, so every invocation sees zeroed counters (self-cleaning).
__device__ float g_h[(size_t)NMAX * HF];            // 25.6 MB
__device__ float g_el[(size_t)NMAX * HEADS];
__device__ float g_er[(size_t)NMAX * HEADS];
__device__ int   g_cnt[NMAX];
__device__ int   g_bucket[(size_t)NMAX * BUCKET];   // 51.2 MB

// ------------------------- f32x2 helpers ------------------------------------
__device__ __forceinline__ void ffma2(ull& d, ull a, ull b) {
    asm("fma.rn.f32x2 %0, %1, %2, %3;" : "=l"(d) : "l"(a), "l"(b), "l"(d));
}
__device__ __forceinline__ ull pack2(float x, float y) {
    ull r; asm("mov.b64 %0, {%1, %2};" : "=l"(r) : "f"(x), "f"(y)); return r;
}
union F4U2 { float4 f4; ull u[2]; };
union U1F2 { ull u; float2 f; };

// ---------------------------------------------------------------------------
// Fused kernel: interleaved gemm-blocks and scatter-blocks in one grid.
//   gemm block  : 32 nodes, h = feat@W via packed f32x2 FMA + el/er reductions
//   scatter     : 256 edges, g_bucket[t*BUCKET + atomicAdd(cnt[t])] = src
// Block roles interleaved (gemm at blockIdx%3==2) so FMA-bound and
// atomic/LSU-bound warps co-reside on each SM and overlap.
// ---------------------------------------------------------------------------
__global__ __launch_bounds__(256) void fused_gemm_scatter_kernel(
    const float* __restrict__ feat, const float* __restrict__ W,
    const float* __restrict__ attn_l, const float* __restrict__ attn_r,
    const int* __restrict__ src, const int* __restrict__ trg,
    int n_nodes, int n_edges, int n_gblk)
{
    __shared__ float Ws[INF * HF];   // 32 KB
    __shared__ float Fs[32 * INF];   // 16 KB

    const int bid = blockIdx.x;
    const int tid = threadIdx.x;
    const bool is_gemm = ((bid % 3) == 2) && (bid / 3 < n_gblk);

    if (!is_gemm) {
        // ---- scatter role ----
        int gemm_before = min((bid + 1) / 3, n_gblk);   // gemm blocks at idx<bid
        int sid = bid - gemm_before;
        int e = sid * 256 + tid;
        if (e < n_edges) {
            int t = trg[e];
            int pos = atomicAdd(&g_cnt[t], 1);
            if (pos < BUCKET) g_bucket[(size_t)t * BUCKET + pos] = src[e];
        }
        return;
    }

    // ---- gemm role ----
    const int base = (bid / 3) * 32;

    #pragma unroll
    for (int i = tid; i < INF * HF / 4; i += 256)
        ((float4*)Ws)[i] = ((const float4*)W)[i];

    for (int i4 = tid; i4 < 32 * INF / 4; i4 += 256) {
        int node = base + (i4 >> 5);
        float4 v = make_float4(0.f, 0.f, 0.f, 0.f);
        if (node < n_nodes)
            v = ((const float4*)feat)[(size_t)node * (INF / 4) + (i4 & 31)];
        ((float4*)Fs)[i4] = v;
    }
    __syncthreads();

    const int cq = tid & 15;          // column quad: cols 4cq .. 4cq+3
    const int np = tid >> 4;          // node pair: nodes 2np, 2np+1
    const float* f0 = &Fs[(2 * np) * INF];
    const float* f1 = f0 + INF;

    ull A0 = 0, A1 = 0, B0 = 0, B1 = 0;   // packed fp32 pairs

    #pragma unroll 8
    for (int k = 0; k < INF; k += 2) {
        float2 fA = *(const float2*)&f0[k];
        float2 fB = *(const float2*)&f1[k];
        F4U2 w0; w0.f4 = *(const float4*)&Ws[k * HF + 4 * cq];
        F4U2 w1; w1.f4 = *(const float4*)&Ws[(k + 1) * HF + 4 * cq];
        ull fa0 = pack2(fA.x, fA.x), fa1 = pack2(fA.y, fA.y);
        ull fb0 = pack2(fB.x, fB.x), fb1 = pack2(fB.y, fB.y);
        ffma2(A0, fa0, w0.u[0]); ffma2(A1, fa0, w0.u[1]);
        ffma2(B0, fb0, w0.u[0]); ffma2(B1, fb0, w0.u[1]);
        ffma2(A0, fa1, w1.u[0]); ffma2(A1, fa1, w1.u[1]);
        ffma2(B0, fb1, w1.u[0]); ffma2(B1, fb1, w1.u[1]);
    }

    U1F2 a0; a0.u = A0;  U1F2 a1; a1.u = A1;   // node0 cols 4cq..4cq+3
    U1F2 b0; b0.u = B0;  U1F2 b1; b1.u = B1;   // node1

    const int n0 = base + 2 * np, n1 = n0 + 1;
    if (n0 < n_nodes)
        *(float4*)&g_h[(size_t)n0 * HF + 4 * cq] =
            make_float4(a0.f.x, a0.f.y, a1.f.x, a1.f.y);
    if (n1 < n_nodes)
        *(float4*)&g_h[(size_t)n1 * HF + 4 * cq] =
            make_float4(b0.f.x, b0.f.y, b1.f.x, b1.f.y);

    // el/er: partial dot per thread, butterfly over the 4 threads of a head.
    float al0 = attn_l[4*cq], al1 = attn_l[4*cq+1], al2 = attn_l[4*cq+2], al3 = attn_l[4*cq+3];
    float ar0 = attn_r[4*cq], ar1 = attn_r[4*cq+1], ar2 = attn_r[4*cq+2], ar3 = attn_r[4*cq+3];

    float el0 = a0.f.x*al0 + a0.f.y*al1 + a1.f.x*al2 + a1.f.y*al3;
    float er0 = a0.f.x*ar0 + a0.f.y*ar1 + a1.f.x*ar2 + a1.f.y*ar3;
    float el1 = b0.f.x*al0 + b0.f.y*al1 + b1.f.x*al2 + b1.f.y*al3;
    float er1 = b0.f.x*ar0 + b0.f.y*ar1 + b1.f.x*ar2 + b1.f.y*ar3;

    #pragma unroll
    for (int off = 1; off <= 2; off <<= 1) {
        el0 += __shfl_xor_sync(0xffffffffu, el0, off);
        er0 += __shfl_xor_sync(0xffffffffu, er0, off);
        el1 += __shfl_xor_sync(0xffffffffu, el1, off);
        er1 += __shfl_xor_sync(0xffffffffu, er1, off);
    }
    if ((cq & 3) == 0) {
        int head = cq >> 2;
        if (n0 < n_nodes) {
            g_el[(size_t)n0 * HEADS + head] = el0;
            g_er[(size_t)n0 * HEADS + head] = er0;
        }
        if (n1 < n_nodes) {
            g_el[(size_t)n1 * HEADS + head] = el1;
            g_er[(size_t)n1 * HEADS + head] = er1;
        }
    }
}

// ---------------------------------------------------------------------------
// Aggregation: 16 threads per node, float4 column slot each. 2-way software
// pipeline (two independent esrc->el/h load chains per iter) for MLP.
// ev recomputed in-loop; reference's global-max shift cancels in ev/denom.
// Lane 0 re-zeroes g_cnt[n] after use (self-cleaning for next invocation).
// ---------------------------------------------------------------------------
__global__ __launch_bounds__(256) void agg_kernel(
    float* __restrict__ out, int n_nodes)
{
    int idx = blockIdx.x * 256 + threadIdx.x;
    int n = idx >> 4;
    if (n >= n_nodes) return;
    int l = idx & 15;          // float4 slot -> cols 4l..4l+3
    int head = l >> 2;

    int cnt = g_cnt[n];
    if (cnt > BUCKET) cnt = BUCKET;
    const int* bkt = &g_bucket[(size_t)n * BUCKET];
    float ern = g_er[(size_t)n * HEADS + head];

    float4 acc = make_float4(0.f, 0.f, 0.f, 0.f);
    float dsum = 0.f;

    int p = 0;
    for (; p + 1 < cnt; p += 2) {
        int s0 = bkt[p], s1 = bkt[p + 1];
        float x0 = g_el[(size_t)s0 * HEADS + head] + ern;
        float x1 = g_el[(size_t)s1 * HEADS + head] + ern;
        float4 h0 = *(const float4*)&g_h[(size_t)s0 * HF + l * 4];
        float4 h1 = *(const float4*)&g_h[(size_t)s1 * HF + l * 4];
        x0 = (x0 > 0.f) ? x0 : 0.2f * x0;
        x1 = (x1 > 0.f) ? x1 : 0.2f * x1;
        float e0 = __expf(x0), e1 = __expf(x1);
        acc.x += e0 * h0.x + e1 * h1.x;
        acc.y += e0 * h0.y + e1 * h1.y;
        acc.z += e0 * h0.z + e1 * h1.z;
        acc.w += e0 * h0.w + e1 * h1.w;
        dsum  += e0 + e1;
    }
    if (p < cnt) {
        int s0 = bkt[p];
        float x0 = g_el[(size_t)s0 * HEADS + head] + ern;
        float4 h0 = *(const float4*)&g_h[(size_t)s0 * HF + l * 4];
        x0 = (x0 > 0.f) ? x0 : 0.2f * x0;
        float e0 = __expf(x0);
        acc.x += e0 * h0.x; acc.y += e0 * h0.y;
        acc.z += e0 * h0.z; acc.w += e0 * h0.w;
        dsum  += e0;
    }

    float inv = 1.0f / (dsum + 1e-16f);
    acc.x *= inv; acc.y *= inv; acc.z *= inv; acc.w *= inv;
    *(float4*)&out[(size_t)n * HF + l * 4] = acc;

    if (l == 0) g_cnt[n] = 0;   // leave counters clean for next invocation
}

// ---------------------------------------------------------------------------
extern "C" void kernel_launch(void* const* d_in, const int* in_sizes, int n_in,
                              void* d_out, int out_size)
{
    const float* feat   = (const float*)d_in[0];
    const float* W      = (const float*)d_in[1];
    const float* attn_l = (const float*)d_in[2];
    const float* attn_r = (const float*)d_in[3];
    const int*   src    = (const int*)d_in[4];
    const int*   trg    = (const int*)d_in[5];
    float* out = (float*)d_out;

    int n_nodes = in_sizes[0] / INF;
    int n_edges = in_sizes[4];

    int n_gblk = (n_nodes + 31) / 32;        // gemm blocks
    int n_sblk = (n_edges + 255) / 256;      // scatter blocks
    int total  = n_gblk + n_sblk;

    fused_gemm_scatter_kernel<<<total, 256>>>(
        feat, W, attn_l, attn_r, src, trg, n_nodes, n_edges, n_gblk);
    agg_kernel<<<((long long)n_nodes * 16 + 255) / 256, 256>>>(out, n_nodes);
}